// round 2
// baseline (speedup 1.0000x reference)
#include <cuda_runtime.h>

// Problem constants (deterministic per reference setup_inputs)
#define NTOT   32768      // 64 graphs * 512 nodes
#define NB     64
#define NPG    512
#define LIG    128
#define GN_PER_G 1020     // global<->same-segment edges per graph (2*127 + 2*383)
#define GG_PER_G 2        // global<->global edges per graph

// Scratch (device globals; no allocation allowed)
__device__ int d_cnt_ctx[NTOT];
__device__ int d_cnt_inter[NTOT];
__device__ int d_off_ctx[NTOT];
__device__ int d_off_inter[NTOT];
__device__ int d_red_cnt[NB];
__device__ int d_red_off[NB];
__device__ int d_tot[4];   // [0]=Ec_radial  [1]=Ei  [2]=Er

// Strict-fp distance matching jnp.linalg.norm(float32): rn ops, no FMA, rn sqrt.
__device__ __forceinline__ float dist_rn(float ax, float ay, float az,
                                         float bx, float by, float bz) {
    float dx = __fadd_rn(ax, -bx);
    float dy = __fadd_rn(ay, -by);
    float dz = __fadd_rn(az, -bz);
    float d2 = __fadd_rn(__fadd_rn(__fmul_rn(dx, dx), __fmul_rn(dy, dy)),
                         __fmul_rn(dz, dz));
    return __fsqrt_rn(d2);
}

__device__ __forceinline__ void pair_preds(const float* __restrict__ X,
                                           int i, int li, int base, int j,
                                           bool& pc, bool& pi, bool& pr) {
    pc = pi = pr = false;
    if (j == li) return;
    bool rg = (li == 0) | (li == LIG);
    bool cg = (j == 0) | (j == LIG);
    if (rg | cg) return;                 // radial & inter need both non-global
    bool rs = (li >= LIG), cs = (j >= LIG);
    if (!rs && !cs) return;              // ligand-ligand: no category
    int col = base + j;
    float ax = X[3 * i],     ay = X[3 * i + 1],     az = X[3 * i + 2];
    float bx = X[3 * col],   by = X[3 * col + 1],   bz = X[3 * col + 2];
    float d = dist_rn(ax, ay, az, bx, by, bz);
    if (rs & cs) {                       // intra-protein context
        pc = (d <= 8.0f);
    } else {                             // inter ligand<->protein
        pi = (d <= 10.0f);
        pr = pi && (li < j);             // reduced: src<dst (ligand side)
    }
}

__global__ void init_kernel() {
    int t = threadIdx.x;
    if (t < NB) d_red_cnt[t] = 0;
}

__global__ void __launch_bounds__(512) count_kernel(const float* __restrict__ X) {
    int i    = blockIdx.x;
    int li   = i & (NPG - 1);
    int b    = i >> 9;
    int base = b * NPG;
    int tid  = threadIdx.x;

    bool pc, pi, pr;
    pair_preds(X, i, li, base, tid, pc, pi, pr);

    __shared__ int sc[16], si[16], sr[16];
    unsigned mc = __ballot_sync(0xffffffffu, pc);
    unsigned mi = __ballot_sync(0xffffffffu, pi);
    unsigned mr = __ballot_sync(0xffffffffu, pr);
    int lane = tid & 31, wid = tid >> 5;
    if (lane == 0) { sc[wid] = __popc(mc); si[wid] = __popc(mi); sr[wid] = __popc(mr); }
    __syncthreads();
    if (tid == 0) {
        int a = 0, c = 0, r = 0;
        #pragma unroll
        for (int w = 0; w < 16; w++) { a += sc[w]; c += si[w]; r += sr[w]; }
        d_cnt_ctx[i]   = a;
        d_cnt_inter[i] = c;
        if (r) atomicAdd(&d_red_cnt[b], r);
    }
}

// ---- single-block exclusive scan ----
__device__ void scan_arr(const int* __restrict__ in, int* __restrict__ outp,
                         int n, int totIdx, int* s, int* s_carry) {
    int tid = threadIdx.x, lane = tid & 31, wid = tid >> 5;
    if (tid == 0) *s_carry = 0;
    __syncthreads();
    for (int bp = 0; bp < n; bp += 1024) {
        int idx = bp + tid;
        int v = (idx < n) ? in[idx] : 0;
        int x = v;
        #pragma unroll
        for (int d = 1; d < 32; d <<= 1) {
            int y = __shfl_up_sync(0xffffffffu, x, d);
            if (lane >= d) x += y;
        }
        if (lane == 31) s[wid] = x;
        __syncthreads();
        if (wid == 0) {
            int t = s[lane];
            #pragma unroll
            for (int d = 1; d < 32; d <<= 1) {
                int y = __shfl_up_sync(0xffffffffu, t, d);
                if (lane >= d) t += y;
            }
            s[lane] = t;
        }
        __syncthreads();
        int inc = x + ((wid > 0) ? s[wid - 1] : 0);
        int carry = *s_carry;
        if (idx < n) outp[idx] = carry + inc - v;   // exclusive
        __syncthreads();
        if (tid == 0) *s_carry = carry + s[31];
        __syncthreads();
    }
    if (tid == 0) d_tot[totIdx] = *s_carry;
    __syncthreads();
}

__global__ void __launch_bounds__(1024) scan_kernel() {
    __shared__ int s[32];
    __shared__ int s_carry;
    scan_arr(d_cnt_ctx,   d_off_ctx,   NTOT, 0, s, &s_carry);
    scan_arr(d_cnt_inter, d_off_inter, NTOT, 1, s, &s_carry);
    scan_arr(d_red_cnt,   d_red_off,   NB,   2, s, &s_carry);
}

// block-ordered rank among predicate-true threads (thread id = ascending col)
__device__ int block_rank512(bool pred, int tid, int* s) {
    int lane = tid & 31, wid = tid >> 5;
    unsigned m = __ballot_sync(0xffffffffu, pred);
    int r = __popc(m & ((1u << lane) - 1u));
    if (lane == 0) s[wid] = __popc(m);
    __syncthreads();
    if (tid == 0) {
        int acc = 0;
        #pragma unroll
        for (int w = 0; w < 16; w++) { int t = s[w]; s[w] = acc; acc += t; }
    }
    __syncthreads();
    r += s[wid];
    __syncthreads();   // allow shared reuse by a subsequent call
    return r;
}

__global__ void __launch_bounds__(512) write_kernel(const float* __restrict__ X,
                                                    float* __restrict__ out) {
    int i    = blockIdx.x;
    int li   = i & (NPG - 1);
    int b    = i >> 9;
    int base = b * NPG;
    int tid  = threadIdx.x;
    int col  = base + tid;

    bool pc, pi, pr;
    pair_preds(X, i, li, base, tid, pc, pi, pr);
    (void)pr;

    int EcR = d_tot[0];
    int Ec  = EcR + NB * (GN_PER_G + GG_PER_G);
    int Ei  = d_tot[1];

    __shared__ int s[16];
    int rc = block_rank512(pc, tid, s);
    if (pc) {
        int o = d_off_ctx[i] + rc;
        out[o]      = (float)i;
        out[Ec + o] = (float)col;
    }
    int ri = block_rank512(pi, tid, s);
    if (pi) {
        int o = 2 * Ec + d_off_inter[i] + ri;
        out[o]      = (float)i;
        out[o + Ei] = (float)col;
    }
}

__global__ void fill_globals(float* __restrict__ out) {
    int b   = blockIdx.x;
    int idx = threadIdx.x;
    if (idx >= GN_PER_G + GG_PER_G) return;
    int EcR  = d_tot[0];
    int Ec   = EcR + NB * (GN_PER_G + GG_PER_G);
    int base = b * NPG;
    int r, c, pos;
    if (idx < GN_PER_G) {
        pos = EcR + b * GN_PER_G + idx;
        if (idx < 127)        { r = 0;               c = 1 + idx; }
        else if (idx < 254)   { r = idx - 126;       c = 0; }
        else if (idx < 637)   { r = 128;             c = idx - 254 + 129; }
        else                  { r = idx - 637 + 129; c = 128; }
    } else {
        int k = idx - GN_PER_G;
        pos = EcR + NB * GN_PER_G + b * 2 + k;
        r = k ? 128 : 0;
        c = k ? 0   : 128;
    }
    out[pos]      = (float)(base + r);
    out[Ec + pos] = (float)(base + c);
}

__global__ void fill_reduced(float* __restrict__ out) {
    int b   = blockIdx.x;
    int Ec  = d_tot[0] + NB * (GN_PER_G + GG_PER_G);
    int Ei  = d_tot[1];
    int Er  = d_tot[2];
    int cnt = d_red_cnt[b];
    int off = d_red_off[b];
    int base1 = 2 * Ec + 2 * Ei + off;
    int base2 = base1 + Er;
    for (int k = threadIdx.x; k < cnt; k += blockDim.x) {
        out[base1 + k] = (float)b;
        out[base2 + k] = (float)(b * NPG);
    }
}

extern "C" void kernel_launch(void* const* d_in, const int* in_sizes, int n_in,
                              void* d_out, int out_size) {
    // Robustly locate X: it is the only input with 3*NTOT elements.
    const float* X = (const float*)d_in[0];
    for (int k = 0; k < n_in; k++) {
        if (in_sizes[k] == 3 * NTOT) { X = (const float*)d_in[k]; break; }
    }
    float* out = (float*)d_out;
    (void)out_size;

    init_kernel<<<1, 64>>>();
    count_kernel<<<NTOT, 512>>>(X);
    scan_kernel<<<1, 1024>>>();
    write_kernel<<<NTOT, 512>>>(X, out);
    fill_globals<<<NB, 1024>>>(out);
    fill_reduced<<<NB, 256>>>(out);
}

// round 3
// speedup vs baseline: 4.8087x; 4.8087x over previous
#include <cuda_runtime.h>

#define NTOT   32768      // 64 graphs * 512 nodes
#define NB     64
#define NPG    512
#define LIG    128
#define GN_PER_G 1020
#define GG_PER_G 2
#define FULL   0xffffffffu

// d <= 8  (d = __fsqrt_rn(d2))  <=>  d2 <= 64 + 1ulp
// d <= 10                       <=>  d2 <= 100 + 1ulp
#define T8_BITS  0x42800001
#define T10_BITS 0x42C80001

// Scratch (device globals; no allocation allowed)
__device__ unsigned d_mask_ctx[NTOT * 16];
__device__ unsigned d_mask_inter[NTOT * 16];
__device__ int d_cnt_ctx[NTOT];
__device__ int d_cnt_inter[NTOT];
__device__ int d_off_ctx[NTOT];
__device__ int d_off_inter[NTOT];
__device__ int d_graph_ctx[NB];
__device__ int d_graph_inter[NB];
__device__ int d_red_cnt[NB];
__device__ int d_goff_ctx[NB];
__device__ int d_goff_inter[NB];
__device__ int d_red_off[NB];
__device__ int d_tot[4];   // [0]=Ec_radial  [1]=Ei  [2]=Er

__device__ __forceinline__ int warp_incl_scan(int x) {
    #pragma unroll
    for (int d = 1; d < 32; d <<= 1) {
        int y = __shfl_up_sync(FULL, x, d);
        if ((threadIdx.x & 31) >= d) x += y;
    }
    return x;
}

__global__ void init_kernel() {
    int t = threadIdx.x;
    if (t < NB) { d_graph_ctx[t] = 0; d_graph_inter[t] = 0; d_red_cnt[t] = 0; }
}

// One warp per row; 16 rows (one block) per 16-row slice of a graph.
__global__ void __launch_bounds__(512) count_kernel(const float* __restrict__ X) {
    __shared__ float s_lin[NPG * 3];           // graph coord tile
    __shared__ int s_bc, s_bi, s_br;
    int tid  = threadIdx.x, lane = tid & 31, wid = tid >> 5;
    int i    = blockIdx.x * 16 + wid;          // global row (block never straddles graphs)
    int b    = i >> 9;
    int base = b << 9;
    int li   = i & (NPG - 1);

    if (tid == 0) { s_bc = 0; s_bi = 0; s_br = 0; }
    const float* gp = X + 3 * base;
    #pragma unroll
    for (int t = tid; t < NPG * 3; t += 512) s_lin[t] = gp[t];
    __syncthreads();

    bool row_global = (li == 0) | (li == LIG);
    bool row_prot   = li > LIG;
    bool row_lig    = (!row_global) && (li < LIG);

    float ax = s_lin[3 * li], ay = s_lin[3 * li + 1], az = s_lin[3 * li + 2];
    const float t8  = __int_as_float(T8_BITS);
    const float t10 = __int_as_float(T10_BITS);

    int cc = 0, ci = 0;
    unsigned mbase = (unsigned)(i << 4);
    #pragma unroll
    for (int k = 0; k < 16; k++) {
        int j = k * 32 + lane;
        bool pc = false, pi = false;
        if (!row_global) {
            bool cg      = (j == 0) | (j == LIG);
            bool cs_prot = j > LIG;
            bool cs_lig  = (!cg) && (j < LIG);
            bool cand    = (j != li) && (!cg);
            bool want_ctx = cand && row_prot && cs_prot;
            bool want_int = cand && ((row_prot && cs_lig) || (row_lig && cs_prot));
            if (want_ctx | want_int) {
                float dx = __fadd_rn(ax, -s_lin[3 * j]);
                float dy = __fadd_rn(ay, -s_lin[3 * j + 1]);
                float dz = __fadd_rn(az, -s_lin[3 * j + 2]);
                float d2 = __fadd_rn(__fadd_rn(__fmul_rn(dx, dx), __fmul_rn(dy, dy)),
                                     __fmul_rn(dz, dz));
                pc = want_ctx && (d2 <= t8);
                pi = want_int && (d2 <= t10);
            }
        }
        unsigned mc = __ballot_sync(FULL, pc);
        unsigned mi = __ballot_sync(FULL, pi);
        if (lane == 0) {
            d_mask_ctx[mbase + k]   = mc;
            d_mask_inter[mbase + k] = mi;
        }
        cc += __popc(mc);
        ci += __popc(mi);
    }
    if (lane == 0) {
        d_cnt_ctx[i]   = cc;
        d_cnt_inter[i] = ci;
        if (cc) atomicAdd(&s_bc, cc);
        if (ci) atomicAdd(&s_bi, ci);
        if (row_lig && ci) atomicAdd(&s_br, ci);
    }
    __syncthreads();
    if (tid == 0) {
        if (s_bc) atomicAdd(&d_graph_ctx[b], s_bc);
        if (s_bi) atomicAdd(&d_graph_inter[b], s_bi);
        if (s_br) atomicAdd(&d_red_cnt[b], s_br);
    }
}

__device__ __forceinline__ void scan64(const int* __restrict__ in,
                                       int* __restrict__ outp, int* tot) {
    int lane = threadIdx.x & 31;
    int v0 = in[2 * lane], v1 = in[2 * lane + 1];
    int s = v0 + v1;
    int x = warp_incl_scan(s);
    int excl = x - s;
    outp[2 * lane]     = excl;
    outp[2 * lane + 1] = excl + v0;
    if (lane == 31) *tot = x;
}

__global__ void tinyscan_kernel() {
    scan64(d_graph_ctx,   d_goff_ctx,   &d_tot[0]);
    scan64(d_graph_inter, d_goff_inter, &d_tot[1]);
    scan64(d_red_cnt,     d_red_off,    &d_tot[2]);
}

__device__ __forceinline__ int block_excl_scan512(int v, int* sw) {
    int lane = threadIdx.x & 31, wid = threadIdx.x >> 5;
    int x = warp_incl_scan(v);
    if (lane == 31) sw[wid] = x;
    __syncthreads();
    if (wid == 0) {
        int t = (lane < 16) ? sw[lane] : 0;
        t = warp_incl_scan(t);
        if (lane < 16) sw[lane] = t;
    }
    __syncthreads();
    int add = wid ? sw[wid - 1] : 0;
    return x - v + add;
}

__global__ void __launch_bounds__(512) rowoff_kernel() {
    __shared__ int sw[16];
    int b = blockIdx.x, t = threadIdx.x;
    int row = (b << 9) + t;
    int v = d_cnt_ctx[row];
    int e = block_excl_scan512(v, sw);
    d_off_ctx[row] = d_goff_ctx[b] + e;
    __syncthreads();
    v = d_cnt_inter[row];
    e = block_excl_scan512(v, sw);
    d_off_inter[row] = d_goff_inter[b] + e;
}

// One warp per row: lanes 0-15 emit ctx words, lanes 16-31 inter words.
__global__ void __launch_bounds__(512) write_kernel(float* __restrict__ out) {
    int tid = threadIdx.x, lane = tid & 31, wid = tid >> 5;
    int i    = blockIdx.x * 16 + wid;
    int base = (i >> 9) << 9;

    bool lower = lane < 16;
    int w = lane & 15;
    unsigned word = lower ? d_mask_ctx[(i << 4) + w] : d_mask_inter[(i << 4) + w];
    int cnt = __popc(word);
    int I = warp_incl_scan(cnt);
    int I15 = __shfl_sync(FULL, I, 15);
    int excl = I - cnt - (lower ? 0 : I15);

    int EcR = d_tot[0];
    int Ec  = EcR + NB * (GN_PER_G + GG_PER_G);
    int Ei  = d_tot[1];
    int rowoff = lower ? d_off_ctx[i] : d_off_inter[i];
    int pos    = lower ? (rowoff + excl) : (2 * Ec + rowoff + excl);
    int colAdd = lower ? Ec : Ei;

    float fi = (float)i;
    int cbase = base + w * 32;
    while (word) {
        int bit = __ffs(word) - 1;
        word &= word - 1;
        out[pos]          = fi;
        out[pos + colAdd] = (float)(cbase + bit);
        pos++;
    }
}

__global__ void __launch_bounds__(1024) fill_kernel(float* __restrict__ out) {
    int b   = blockIdx.x;
    int idx = threadIdx.x;
    int EcR  = d_tot[0];
    int Ec   = EcR + NB * (GN_PER_G + GG_PER_G);
    int Ei   = d_tot[1];
    int Er   = d_tot[2];
    int base = b * NPG;

    if (idx < GN_PER_G + GG_PER_G) {
        int r, c, pos;
        if (idx < GN_PER_G) {
            pos = EcR + b * GN_PER_G + idx;
            if (idx < 127)        { r = 0;               c = 1 + idx; }
            else if (idx < 254)   { r = idx - 126;       c = 0; }
            else if (idx < 637)   { r = 128;             c = idx - 254 + 129; }
            else                  { r = idx - 637 + 129; c = 128; }
        } else {
            int k = idx - GN_PER_G;
            pos = EcR + NB * GN_PER_G + b * 2 + k;
            r = k ? 128 : 0;
            c = k ? 0   : 128;
        }
        out[pos]      = (float)(base + r);
        out[Ec + pos] = (float)(base + c);
    }

    int cnt = d_red_cnt[b];
    int off = d_red_off[b];
    int base1 = 2 * Ec + 2 * Ei + off;
    int base2 = base1 + Er;
    float fb = (float)b, fo = (float)(b * NPG);
    for (int k = idx; k < cnt; k += 1024) {
        out[base1 + k] = fb;
        out[base2 + k] = fo;
    }
}

extern "C" void kernel_launch(void* const* d_in, const int* in_sizes, int n_in,
                              void* d_out, int out_size) {
    const float* X = (const float*)d_in[0];
    for (int k = 0; k < n_in; k++) {
        if (in_sizes[k] == 3 * NTOT) { X = (const float*)d_in[k]; break; }
    }
    float* out = (float*)d_out;
    (void)out_size;

    init_kernel<<<1, 64>>>();
    count_kernel<<<NTOT / 16, 512>>>(X);
    tinyscan_kernel<<<1, 32>>>();
    rowoff_kernel<<<NB, 512>>>();
    write_kernel<<<NTOT / 16, 512>>>(out);
    fill_kernel<<<NB, 1024>>>(out);
}

// round 4
// speedup vs baseline: 5.8000x; 1.2062x over previous
#include <cuda_runtime.h>

#define NTOT   32768      // 64 graphs * 512 nodes
#define NB     64
#define NPG    512
#define LIG    128
#define GN_PER_G 1020
#define GG_PER_G 2
#define GFIX   (NB * (GN_PER_G + GG_PER_G))   // 65408
#define FULL   0xffffffffu

// d = __fsqrt_rn(d2);  d <= 8  <=>  d2 <= 64+1ulp ;  d <= 10 <=> d2 <= 100+1ulp
#define T8_BITS  0x42800001
#define T10_BITS 0x42C80001

// Scratch (device globals; no allocation allowed)
__device__ unsigned d_mask_ctx[NTOT * 16];
__device__ unsigned d_mask_inter[NTOT * 16];
__device__ int d_cnt_ctx[NTOT];
__device__ int d_cnt_inter[NTOT];
__device__ int d_off_ctx[NTOT];     // local (within-graph) exclusive row offsets
__device__ int d_off_inter[NTOT];
__device__ int d_graph_ctx[NB];     // per-graph totals
__device__ int d_graph_inter[NB];
__device__ int d_red_cnt[NB];

__device__ __forceinline__ int warp_incl_scan(int x) {
    #pragma unroll
    for (int d = 1; d < 32; d <<= 1) {
        int y = __shfl_up_sync(FULL, x, d);
        if ((threadIdx.x & 31) >= d) x += y;
    }
    return x;
}

// One warp scans a 64-int array: exclusive prefix -> sh_excl[64], total -> *sh_tot.
__device__ __forceinline__ void warp_scan64_sh(const int* __restrict__ in,
                                               int* sh_excl, int* sh_tot) {
    int lane = threadIdx.x & 31;
    int v0 = in[2 * lane], v1 = in[2 * lane + 1];
    int s = v0 + v1;
    int x = warp_incl_scan(s);
    int excl = x - s;
    sh_excl[2 * lane]     = excl;
    sh_excl[2 * lane + 1] = excl + v0;
    if (lane == 31) *sh_tot = x;
}

// ---------------- count: one warp per row, 16 rows per block ----------------
__global__ void __launch_bounds__(512) count_kernel(const float* __restrict__ X) {
    __shared__ float4 s_pos[NPG];              // padded coords, 8KB
    int tid  = threadIdx.x, lane = tid & 31, wid = tid >> 5;
    int i    = blockIdx.x * 16 + wid;          // blocks never straddle graphs
    int b    = i >> 9;
    int base = b << 9;
    int li   = i & (NPG - 1);

    const float* gp = X + 3 * base;
    {
        int t = tid;                            // 512 threads, one node each
        s_pos[t] = make_float4(gp[3 * t], gp[3 * t + 1], gp[3 * t + 2], 0.f);
    }
    __syncthreads();

    bool row_global = (li == 0) | (li == LIG);
    bool row_prot   = li > LIG;

    float4 a = s_pos[li];
    const float t8  = __int_as_float(T8_BITS);
    const float t10 = __int_as_float(T10_BITS);

    int cc = 0, ci = 0;
    unsigned mbase = (unsigned)(i << 4);

    auto doK = [&](int k) {
        int j = k * 32 + lane;
        float4 p = s_pos[k * 32 + lane];
        float dx = __fadd_rn(a.x, -p.x);
        float dy = __fadd_rn(a.y, -p.y);
        float dz = __fadd_rn(a.z, -p.z);
        float d2 = __fadd_rn(__fadd_rn(__fmul_rn(dx, dx), __fmul_rn(dy, dy)),
                             __fmul_rn(dz, dz));
        bool cg      = (j == 0) | (j == LIG);
        bool cs_prot = j > LIG;
        bool cs_lig  = (!cg) && (j < LIG);
        bool pc, pi;
        if (row_prot) {
            pc = cs_prot && (j != li) && (d2 <= t8);
            pi = cs_lig  && (d2 <= t10);
        } else {                                 // ligand row (j >= 129 only reach here)
            pc = false;
            pi = cs_prot && (d2 <= t10);
        }
        unsigned mc = __ballot_sync(FULL, pc);
        unsigned mi = __ballot_sync(FULL, pi);
        if (lane == 0) {
            d_mask_ctx[mbase + k]   = mc;
            d_mask_inter[mbase + k] = mi;
        }
        cc += __popc(mc);
        ci += __popc(mi);
    };

    if (row_global) {
        if (lane < 16) {
            d_mask_ctx[mbase + lane]   = 0u;
            d_mask_inter[mbase + lane] = 0u;
        }
    } else if (row_prot) {
        #pragma unroll
        for (int k = 0; k < 16; k++) doK(k);
    } else {                                     // ligand: cols 0..127 are never edges
        if (lane < 4) {
            d_mask_ctx[mbase + lane]   = 0u;
            d_mask_inter[mbase + lane] = 0u;
        }
        #pragma unroll
        for (int k = 4; k < 16; k++) doK(k);
    }

    if (lane == 0) {
        d_cnt_ctx[i]   = cc;
        d_cnt_inter[i] = ci;
    }
}

// ---------------- per-graph row scans + graph totals (no atomics) ----------------
__device__ __forceinline__ int block_excl_scan512(int v, int* sw) {
    int lane = threadIdx.x & 31, wid = threadIdx.x >> 5;
    int x = warp_incl_scan(v);
    if (lane == 31) sw[wid] = x;
    __syncthreads();
    if (wid == 0) {
        int t = (lane < 16) ? sw[lane] : 0;
        t = warp_incl_scan(t);
        if (lane < 16) sw[lane] = t;
    }
    __syncthreads();
    int add = wid ? sw[wid - 1] : 0;
    return x - v + add;
}

__global__ void __launch_bounds__(512) scanrow_kernel() {
    __shared__ int sw[16];
    __shared__ int sred;
    int b = blockIdx.x, t = threadIdx.x;
    int row = (b << 9) + t;
    if (t == 0) sred = 0;

    int vc = d_cnt_ctx[row];
    int ec = block_excl_scan512(vc, sw);
    d_off_ctx[row] = ec;
    if (t == 511) d_graph_ctx[b] = ec + vc;
    __syncthreads();

    int vi = d_cnt_inter[row];
    int ei = block_excl_scan512(vi, sw);
    d_off_inter[row] = ei;
    if (t == 511) d_graph_inter[b] = ei + vi;

    int vr = (t >= 1 && t < LIG) ? vi : 0;       // reduced = ligand-row inter edges
    #pragma unroll
    for (int d = 16; d; d >>= 1) vr += __shfl_down_sync(FULL, vr, d);
    if ((t & 31) == 0 && vr) atomicAdd(&sred, vr);
    __syncthreads();
    if (t == 0) d_red_cnt[b] = sred;
}

// ---------------- write: one warp per row; redundant in-block 64-scans ----------------
__global__ void __launch_bounds__(512) write_kernel(float* __restrict__ out) {
    __shared__ int sgc[NB], sgi[NB];
    __shared__ int stc, sti;
    int tid = threadIdx.x, lane = tid & 31, wid = tid >> 5;
    int i    = blockIdx.x * 16 + wid;
    int b    = i >> 9;
    int base = b << 9;

    if (wid == 0)      warp_scan64_sh(d_graph_ctx,   sgc, &stc);
    else if (wid == 1) warp_scan64_sh(d_graph_inter, sgi, &sti);
    __syncthreads();

    bool lower = lane < 16;
    int w = lane & 15;
    unsigned word = lower ? d_mask_ctx[(i << 4) + w] : d_mask_inter[(i << 4) + w];
    int cnt = __popc(word);
    int I = warp_incl_scan(cnt);
    int I15 = __shfl_sync(FULL, I, 15);
    int excl = I - cnt - (lower ? 0 : I15);

    int Ec = stc + GFIX;
    int Ei = sti;
    int rowoff = lower ? (sgc[b] + d_off_ctx[i]) : (sgi[b] + d_off_inter[i]);
    int pos    = lower ? (rowoff + excl) : (2 * Ec + rowoff + excl);
    int colAdd = lower ? Ec : Ei;

    float fi = (float)i;
    int cbase = base + w * 32;
    while (word) {
        int bit = __ffs(word) - 1;
        word &= word - 1;
        out[pos]          = fi;
        out[pos + colAdd] = (float)(cbase + bit);
        pos++;
    }
}

// ---------------- fixed global edges + reduced arrays ----------------
__global__ void __launch_bounds__(1024) fill_kernel(float* __restrict__ out) {
    __shared__ int sdc[NB], sdi[NB], sro[NB];
    __shared__ int stc, sti, str;
    int b   = blockIdx.x;
    int idx = threadIdx.x;
    int wid = idx >> 5;

    if (wid == 0)      warp_scan64_sh(d_graph_ctx,   sdc, &stc);
    else if (wid == 1) warp_scan64_sh(d_graph_inter, sdi, &sti);
    else if (wid == 2) warp_scan64_sh(d_red_cnt,     sro, &str);
    __syncthreads();

    int EcR = stc;
    int Ec  = EcR + GFIX;
    int Ei  = sti;
    int Er  = str;
    int base = b * NPG;

    if (idx < GN_PER_G + GG_PER_G) {
        int r, c, pos;
        if (idx < GN_PER_G) {
            pos = EcR + b * GN_PER_G + idx;
            if (idx < 127)        { r = 0;               c = 1 + idx; }
            else if (idx < 254)   { r = idx - 126;       c = 0; }
            else if (idx < 637)   { r = 128;             c = idx - 254 + 129; }
            else                  { r = idx - 637 + 129; c = 128; }
        } else {
            int k = idx - GN_PER_G;
            pos = EcR + NB * GN_PER_G + b * 2 + k;
            r = k ? 128 : 0;
            c = k ? 0   : 128;
        }
        out[pos]      = (float)(base + r);
        out[Ec + pos] = (float)(base + c);
    }

    int cnt = d_red_cnt[b];
    int off = sro[b];
    int base1 = 2 * Ec + 2 * Ei + off;
    int base2 = base1 + Er;
    float fb = (float)b, fo = (float)base;
    for (int k = idx; k < cnt; k += 1024) {
        out[base1 + k] = fb;
        out[base2 + k] = fo;
    }
}

extern "C" void kernel_launch(void* const* d_in, const int* in_sizes, int n_in,
                              void* d_out, int out_size) {
    const float* X = (const float*)d_in[0];
    for (int k = 0; k < n_in; k++) {
        if (in_sizes[k] == 3 * NTOT) { X = (const float*)d_in[k]; break; }
    }
    float* out = (float*)d_out;
    (void)out_size;

    count_kernel<<<NTOT / 16, 512>>>(X);
    scanrow_kernel<<<NB, 512>>>();
    write_kernel<<<NTOT / 16, 512>>>(out);
    fill_kernel<<<NB, 1024>>>(out);
}